// round 14
// baseline (speedup 1.0000x reference)
#include <cuda_runtime.h>
#include <cuda_fp16.h>
#include <cstdint>

// 2-layer LSTM scan, B=1024, H=64, S=512. R14 = R13 + exact micro-cuts:
//  - sigmoid 1/2-scale folded into fp16 weights/biases at pack time (rows
//    i,f,o scaled by 0.5; G untouched) -> no pre-tanh FMULs, shorter chains.
//  - out-finalize spread across warps 0-7 (warp b reduces batch b).
// Warp w owns gate rows {gate*64 + 4w + jj}; lane pair (L, L^16) holds all 4
// gates for (j, 2 batches); in-warp activations; 1 __syncthreads()/step.
// h permuted fp16 single-plane (2x LDS.128/operand), x transposed [t][b].
// A = single-pass fp16 in registers. 12 HMMA/warp/step.

#define HID 64
#define NB  8
#define TPB 512
#define BATCH 1024
#define SEQ 512
#define NCTA (BATCH/NB)      // 128
#define HSW 36               // h row stride in words (32 + 4 pad)

__device__ __forceinline__ uint32_t packh(float a, float b) {
    __half2 v = __floats2half2_rn(a, b);
    return *(uint32_t*)&v;
}
__device__ __forceinline__ void mma16816(float* d, const uint32_t* a,
                                         uint32_t b0, uint32_t b1) {
    asm("mma.sync.aligned.m16n8k16.row.col.f32.f16.f16.f32 "
        "{%0,%1,%2,%3}, {%4,%5,%6,%7}, {%8,%9}, {%0,%1,%2,%3};"
        : "+f"(d[0]), "+f"(d[1]), "+f"(d[2]), "+f"(d[3])
        : "r"(a[0]), "r"(a[1]), "r"(a[2]), "r"(a[3]), "r"(b0), "r"(b1));
}
__device__ __forceinline__ float ftanh(float x) {
    float y; asm("tanh.approx.f32 %0, %1;" : "=f"(y) : "f"(x)); return y;
}

__global__ __launch_bounds__(TPB, 1)
void lstm_kernel(const float* __restrict__ input,
                 const float* __restrict__ W_ih1, const float* __restrict__ W_hh1,
                 const float* __restrict__ b_ih1, const float* __restrict__ b_hh1,
                 const float* __restrict__ W_ih2, const float* __restrict__ W_hh2,
                 const float* __restrict__ b_ih2, const float* __restrict__ b_hh2,
                 const float* __restrict__ W_lin, const float* __restrict__ b_lin,
                 float* __restrict__ out)
{
    __shared__ uint32_t hs1[2][NB][HSW];   // h1, permuted fp16 pairs, parity-buffered
    __shared__ uint32_t hs2[2][NB][HSW];   // h2
    __shared__ float xs2[SEQ * NB];        // inputs transposed [t][b] (16 KB)
    __shared__ float reds[2][128];         // out partials [parity][w*8 + b]

    const int tid  = threadIdx.x;
    const int w    = tid >> 5, lane = tid & 31;
    const int g    = lane >> 2, tq = lane & 3;
    const bool low = (g < 4);
    const int jj   = g & 3;
    const int j    = 4 * w + jj;           // hidden index this lane-pair owns
    const int b0   = blockIdx.x * NB;
    const int bmy  = 2 * tq + (low ? 0 : 1);   // batch this lane acts on
    const bool red_lane = ((lane & 12) == 0);

    // Permuted store offset for h[j] within a batch row (bytes)
    const int wd   = j >> 1;
    const int hq   = (wd & 3) * 8 + (wd >> 2);
    const int hoff = hq * 4 + (j & 1) * 2;

    // Gate rows: low pair = (i, G); high pair = (f, o)
    const int rowA = (low ? 0 : 1) * HID + j;   // i or f  (sigmoid: scale 0.5)
    const int rowB = (low ? 2 : 3) * HID + j;   // G or o  (G: 1.0, o: 0.5)
    const float scA = 0.5f;
    const float scB = low ? 1.0f : 0.5f;

    // ---- Persistent A-fragments, single fp16, scale-folded, registers only ----
    uint32_t wa1[4][4];                    // W_hh1
    uint32_t wa2[8][4];                    // [W_ih2|W_hh2]
    #pragma unroll
    for (int kt = 0; kt < 4; kt++) {
        int cb = kt * 16 + 2 * tq;
        wa1[kt][0] = packh(scA*W_hh1[rowA*HID+cb],   scA*W_hh1[rowA*HID+cb+1]);
        wa1[kt][1] = packh(scB*W_hh1[rowB*HID+cb],   scB*W_hh1[rowB*HID+cb+1]);
        wa1[kt][2] = packh(scA*W_hh1[rowA*HID+cb+8], scA*W_hh1[rowA*HID+cb+9]);
        wa1[kt][3] = packh(scB*W_hh1[rowB*HID+cb+8], scB*W_hh1[rowB*HID+cb+9]);
    }
    #pragma unroll
    for (int kt = 0; kt < 8; kt++) {
        int cb = kt * 16 + 2 * tq;
        #pragma unroll
        for (int r = 0; r < 4; r++) {
            int row = (r & 1) ? rowB : rowA;
            float sc = (r & 1) ? scB : scA;
            int k   = cb + ((r >= 2) ? 8 : 0);
            float v0 = (k < HID)     ? W_ih2[row*HID + k]     : W_hh2[row*HID + k - HID];
            float v1 = (k + 1 < HID) ? W_ih2[row*HID + k + 1] : W_hh2[row*HID + k + 1 - HID];
            wa2[kt][r] = packh(sc * v0, sc * v1);
        }
    }

    // ---- Per-lane scalar constants (scale-folded) ----
    const float bA1 = scA * (b_ih1[rowA] + b_hh1[rowA]);
    const float bB1 = scB * (b_ih1[rowB] + b_hh1[rowB]);
    const float bA2 = scA * (b_ih2[rowA] + b_hh2[rowA]);
    const float bB2 = scB * (b_ih2[rowB] + b_hh2[rowB]);
    const float wxA = scA * W_ih1[rowA];
    const float wxB = scB * W_ih1[rowB];
    const float wlj = W_lin[j];
    const float blin = b_lin[0];
    const float pBm = low ? 1.0f : 0.5f;   // G: tanh; o: sigmoid epilogue
    const float pBa = low ? 0.0f : 0.5f;

    // ---- Init SMEM ----
    for (int i = tid; i < 2 * NB * HSW; i += TPB) {
        ((uint32_t*)hs1)[i] = 0;
        ((uint32_t*)hs2)[i] = 0;
    }
    for (int i = tid; i < NB * SEQ; i += TPB) {
        int b = i >> 9, t = i & 511;       // coalesced gmem read
        xs2[t * NB + b] = input[(b0 + b) * SEQ + t];
    }
    __syncthreads();

    float c1 = 0.f, c2 = 0.f;

    // ---- Peel act1(0): gates = wx*x(0) + bias (h1(-1)=0), write hs1[0] ----
    {
        float2 xp = *(const float2*)&xs2[0 * NB + 2 * tq];
        float vA0 = fmaf(wxA, xp.x, bA1), vA1 = fmaf(wxA, xp.y, bA1);
        float vB0 = fmaf(wxB, xp.x, bB1), vB1 = fmaf(wxB, xp.y, bB1);
        float tA0 = ftanh(vA0), tA1 = ftanh(vA1);
        float tB0 = ftanh(vB0), tB1 = ftanh(vB1);
        float uA0 = fmaf(0.5f,tA0,0.5f), uA1 = fmaf(0.5f,tA1,0.5f);
        float uB0 = fmaf(pBm,tB0,pBa),   uB1 = fmaf(pBm,tB1,pBa);
        float prod0 = uA0*uB0, prod1 = uA1*uB1;
        float r1 = __shfl_xor_sync(0xFFFFFFFFu, low ? prod1 : uA0, 16);
        float r2 = __shfl_xor_sync(0xFFFFFFFFu, low ? 0.f   : uB0, 16);
        float my_sf = low ? r1 : uA1;
        float my_pr = low ? prod0 : r1;
        float cn = fmaf(my_sf, c1, my_pr); c1 = cn;
        float tcn = ftanh(cn);
        float my_so = low ? r2 : uB1;
        float h = my_so * tcn;
        *(__half*)((char*)&hs1[0][bmy][0] + hoff) = __float2half_rn(h);
    }
    __syncthreads();

    #pragma unroll 2
    for (int ts = 0; ts < SEQ; ts++) {
        const int p = ts & 1, pn = p ^ 1;

        // ---- Load B-frags: 2x LDS.128 per operand half ----
        const uint4* h1p = (const uint4*)&hs1[p][g][tq * 8];
        const uint4* h2p = (const uint4*)&hs2[pn][g][tq * 8];
        uint4 h1a = h1p[0], h1b = h1p[1];
        uint4 h2a = h2p[0], h2b = h2p[1];

        // ---- finalize out(ts-1): warp b reduces batch b (spread) ----
        if (ts > 0 && w < NB) {
            float s = (lane < 16) ? reds[pn][lane * 8 + w] : 0.f;
            s += __shfl_xor_sync(0xFFFFFFFFu, s, 8);
            s += __shfl_xor_sync(0xFFFFFFFFu, s, 4);
            s += __shfl_xor_sync(0xFFFFFFFFu, s, 2);
            s += __shfl_xor_sync(0xFFFFFFFFu, s, 1);
            if (lane == 0) out[(b0 + w) * SEQ + (ts - 1)] = s + blin;
        }

        // ---- MMA2(t): bias-initialized accumulators ----
        float d[4]  = {bA2, bA2, bB2, bB2};
        float d2[4] = {0.f, 0.f, 0.f, 0.f};
        mma16816(d,  wa2[0], h1a.x, h1a.y);
        mma16816(d2, wa2[1], h1a.z, h1a.w);
        mma16816(d,  wa2[2], h1b.x, h1b.y);
        mma16816(d2, wa2[3], h1b.z, h1b.w);
        mma16816(d,  wa2[4], h2a.x, h2a.y);
        mma16816(d2, wa2[5], h2a.z, h2a.w);
        mma16816(d,  wa2[6], h2b.x, h2b.y);
        mma16816(d2, wa2[7], h2b.z, h2b.w);

        // ---- MMA1(t+1): issued BEFORE act2 so its latency hides under it ----
        float e[4], e2[4];
        const bool has_next = (ts + 1 < SEQ);
        if (has_next) {
            float2 xp = *(const float2*)&xs2[(ts + 1) * NB + 2 * tq];
            e[0] = fmaf(wxA, xp.x, bA1); e[1] = fmaf(wxA, xp.y, bA1);
            e[2] = fmaf(wxB, xp.x, bB1); e[3] = fmaf(wxB, xp.y, bB1);
            e2[0] = e2[1] = e2[2] = e2[3] = 0.f;
            mma16816(e,  wa1[0], h1a.x, h1a.y);
            mma16816(e2, wa1[1], h1a.z, h1a.w);
            mma16816(e,  wa1[2], h1b.x, h1b.y);
            mma16816(e2, wa1[3], h1b.z, h1b.w);
        }

        // ---- act2(t): in-warp; writes hs2[p], reds[p] ----
        {
            float vA0 = d[0] + d2[0], vA1 = d[1] + d2[1];
            float vB0 = d[2] + d2[2], vB1 = d[3] + d2[3];
            float tA0 = ftanh(vA0), tA1 = ftanh(vA1);
            float tB0 = ftanh(vB0), tB1 = ftanh(vB1);
            float uA0 = fmaf(0.5f,tA0,0.5f), uA1 = fmaf(0.5f,tA1,0.5f);
            float uB0 = fmaf(pBm,tB0,pBa),   uB1 = fmaf(pBm,tB1,pBa);
            float prod0 = uA0*uB0, prod1 = uA1*uB1;
            float r1 = __shfl_xor_sync(0xFFFFFFFFu, low ? prod1 : uA0, 16);
            float r2 = __shfl_xor_sync(0xFFFFFFFFu, low ? 0.f   : uB0, 16);
            float my_sf = low ? r1 : uA1;
            float my_pr = low ? prod0 : r1;
            float cn = fmaf(my_sf, c2, my_pr); c2 = cn;
            float tcn = ftanh(cn);
            float my_so = low ? r2 : uB1;
            float h = my_so * tcn;
            *(__half*)((char*)&hs2[p][bmy][0] + hoff) = __float2half_rn(h);
            float v = wlj * h;
            v += __shfl_xor_sync(0xFFFFFFFFu, v, 4);
            v += __shfl_xor_sync(0xFFFFFFFFu, v, 8);
            if (red_lane) reds[p][w * 8 + bmy] = v;
        }

        // ---- act1(t+1): MMA1 results long since ready ----
        if (has_next) {
            float vA0 = e[0] + e2[0], vA1 = e[1] + e2[1];
            float vB0 = e[2] + e2[2], vB1 = e[3] + e2[3];
            float tA0 = ftanh(vA0), tA1 = ftanh(vA1);
            float tB0 = ftanh(vB0), tB1 = ftanh(vB1);
            float uA0 = fmaf(0.5f,tA0,0.5f), uA1 = fmaf(0.5f,tA1,0.5f);
            float uB0 = fmaf(pBm,tB0,pBa),   uB1 = fmaf(pBm,tB1,pBa);
            float prod0 = uA0*uB0, prod1 = uA1*uB1;
            float r1 = __shfl_xor_sync(0xFFFFFFFFu, low ? prod1 : uA0, 16);
            float r2 = __shfl_xor_sync(0xFFFFFFFFu, low ? 0.f   : uB0, 16);
            float my_sf = low ? r1 : uA1;
            float my_pr = low ? prod0 : r1;
            float cn = fmaf(my_sf, c1, my_pr); c1 = cn;
            float tcn = ftanh(cn);
            float my_so = low ? r2 : uB1;
            float h = my_so * tcn;
            *(__half*)((char*)&hs1[pn][bmy][0] + hoff) = __float2half_rn(h);
        }
        __syncthreads();
    }

    // ---- finalize out(SEQ-1): spread across warps 0-7 ----
    if (w < NB) {
        const int pl = (SEQ - 1) & 1;
        float s = (lane < 16) ? reds[pl][lane * 8 + w] : 0.f;
        s += __shfl_xor_sync(0xFFFFFFFFu, s, 8);
        s += __shfl_xor_sync(0xFFFFFFFFu, s, 4);
        s += __shfl_xor_sync(0xFFFFFFFFu, s, 2);
        s += __shfl_xor_sync(0xFFFFFFFFu, s, 1);
        if (lane == 0) out[(b0 + w) * SEQ + (SEQ - 1)] = s + blin;
    }
}

extern "C" void kernel_launch(void* const* d_in, const int* in_sizes, int n_in,
                              void* d_out, int out_size) {
    (void)in_sizes; (void)n_in; (void)out_size;
    const float* input = (const float*)d_in[0];
    const float* W_ih1 = (const float*)d_in[1];
    const float* W_hh1 = (const float*)d_in[2];
    const float* b_ih1 = (const float*)d_in[3];
    const float* b_hh1 = (const float*)d_in[4];
    const float* W_ih2 = (const float*)d_in[5];
    const float* W_hh2 = (const float*)d_in[6];
    const float* b_ih2 = (const float*)d_in[7];
    const float* b_hh2 = (const float*)d_in[8];
    const float* W_lin = (const float*)d_in[9];
    const float* b_lin = (const float*)d_in[10];
    float* out = (float*)d_out;

    lstm_kernel<<<NCTA, TPB>>>(input, W_ih1, W_hh1, b_ih1, b_hh1,
                               W_ih2, W_hh2, b_ih2, b_hh2,
                               W_lin, b_lin, out);
}